// round 3
// baseline (speedup 1.0000x reference)
#include <cuda_runtime.h>
#include <cstdint>

// ---------------------------------------------------------------------------
// SG_RSNN: 33-step recurrent spiking network.
//   inputs: v_m, i_syn, rate, spike, x, kernel_in, kernel_h, kernel_out
//   output: concat(out[8192x128], v_m, i_syn, rate, spike each [8192x512])
//
// Numerical-matching strategy (reference = JAX/XLA:GPU, fp32):
//  * GEMMs: cublas-style single FMA chain per output element, k ascending,
//    scalar R applied as a post-multiply (cublas alpha).
//  * spike @ kernel_h done sparsely from bitmasks in increasing-j order:
//    bit-identical to the dense sequential FMA chain since spike in {0,1}.
//  * i_in uses concat(x,-x) @ kernel_in literally (sign on x, k=0..511 order).
//  * Elementwise LIF updates use fmaf in the shapes ptxas contraction
//    produces from XLA's mul/add PTX:
//      isyn = fma(isyn, a_syn, ispike)
//      v    = fma(a_vm,  v - s,   s)
//      rate = fma(a_out, rate - t, t)
// ---------------------------------------------------------------------------

#define BATCH    8192
#define IN_DIMS  256
#define NN       512
#define OUT_DIMS 128
#define NSTEPS   33

#define NSLICES  8
#define NGROUPS  16
#define GROUP_ROWS 512
#define SLICE_COLS 64

#define ALPHA_SYN 0.90483741803595957f   // exp(-0.1)
#define ALPHA_VM  0.95122942450071401f   // exp(-0.05)
#define ALPHA_OUT 0.95122942450071401f
#define R_IN   0.08838834764831844f      // 0.1*1*10*sqrt(2/256)
#define R_H    0.125f                    // exact
#define R_OUT  0.22097086912079611f      // 5*sqrt(1/512)
#define VTH    1.0f

__device__ float    g_iin [BATCH * NN];
__device__ float    g_vm  [BATCH * NN];
__device__ float    g_isyn[BATCH * NN];
__device__ float    g_rate[BATCH * NN];
__device__ unsigned g_maskA[BATCH * 16];
__device__ unsigned g_maskB[BATCH * 16];

// ---------------------------------------------------------------------------
__global__ void k_init(const float* __restrict__ vm0, const float* __restrict__ is0,
                       const float* __restrict__ rt0, const float* __restrict__ sp0)
{
    int tid  = blockIdx.x * blockDim.x + threadIdx.x;
    int nthr = gridDim.x * blockDim.x;
    for (int i = tid; i < BATCH * NN; i += nthr) {
        g_vm[i]   = vm0[i];
        g_isyn[i] = is0[i];
        g_rate[i] = rt0[i];
    }
    for (int w = tid; w < BATCH * 16; w += nthr) {
        int b = w >> 4, wi = w & 15;
        const float* sp = sp0 + b * NN + wi * 32;
        unsigned m = 0;
        #pragma unroll
        for (int j = 0; j < 32; j++)
            m |= (sp[j] != 0.0f ? 1u : 0u) << j;
        g_maskA[w] = m;
    }
}

// ---------------------------------------------------------------------------
// i_in GEMM: acc[b][n] = sum_{k=0..511} a_k * kin[k][n],  a = concat(x, -x)[b]
// Strict sequential-k order, single FMA accumulator. Then *R_IN.
__global__ void k_iin(const float* __restrict__ x, const float* __restrict__ kin)
{
    __shared__ float As[16][64];
    __shared__ float Bs[16][65];
    int bn0 = blockIdx.x * 64;
    int bm0 = blockIdx.y * 64;
    int t = threadIdx.x;
    int tx = t & 15, ty = t >> 4;
    float acc[4][4];
    #pragma unroll
    for (int i = 0; i < 4; i++)
        #pragma unroll
        for (int j = 0; j < 4; j++) acc[i][j] = 0.0f;

    for (int k0 = 0; k0 < 2 * IN_DIMS; k0 += 16) {
        #pragma unroll
        for (int q = 0; q < 4; q++) {
            int li = t + q * 256;
            int i  = li >> 4;
            int kk = li & 15;
            int k  = k0 + kk;
            float xv = x[(bm0 + i) * IN_DIMS + (k & (IN_DIMS - 1))];
            As[kk][i] = (k < IN_DIMS) ? xv : -xv;
        }
        #pragma unroll
        for (int q = 0; q < 4; q++) {
            int li = t + q * 256;
            int kk = li >> 6;
            int n  = li & 63;
            Bs[kk][n] = kin[(k0 + kk) * NN + bn0 + n];
        }
        __syncthreads();
        #pragma unroll
        for (int kk = 0; kk < 16; kk++) {
            float a[4], bq[4];
            #pragma unroll
            for (int i = 0; i < 4; i++) a[i]  = As[kk][ty * 4 + i];
            #pragma unroll
            for (int j = 0; j < 4; j++) bq[j] = Bs[kk][tx * 4 + j];
            #pragma unroll
            for (int i = 0; i < 4; i++)
                #pragma unroll
                for (int j = 0; j < 4; j++)
                    acc[i][j] = fmaf(a[i], bq[j], acc[i][j]);
        }
        __syncthreads();
    }
    #pragma unroll
    for (int i = 0; i < 4; i++)
        #pragma unroll
        for (int j = 0; j < 4; j++)
            g_iin[(bm0 + ty * 4 + i) * NN + bn0 + tx * 4 + j] =
                __fmul_rn(R_IN, acc[i][j]);
}

// ---------------------------------------------------------------------------
// Elementwise LIF update, fma shapes matching ptxas-contracted XLA code:
//   i_spike = R * acc
//   i_syn   = fma(i_syn, a_syn, i_spike)
//   s = i_syn + i_in ; v = fma(a_vm, v - s, s)
//   spike = v > vth ; v = (1-spike)*v
//   rate  = fma(a_out, rate - t, t), t = 2*spike
__device__ __forceinline__ bool update_cell(int cell, float acc)
{
    float isyn = g_isyn[cell];
    float iin  = g_iin [cell];
    float v    = g_vm  [cell];
    float rate = g_rate[cell];

    float ispike = __fmul_rn(R_H, acc);
    isyn = fmaf(isyn, ALPHA_SYN, ispike);
    float s = __fadd_rn(isyn, iin);
    v = fmaf(ALPHA_VM, __fsub_rn(v, s), s);
    bool sp = v > VTH;
    v = sp ? 0.0f : v;
    float tgt = sp ? 2.0f : 0.0f;
    rate = fmaf(ALPHA_OUT, __fsub_rn(rate, tgt), tgt);

    g_isyn[cell] = isyn;
    g_vm  [cell] = v;
    g_rate[cell] = rate;
    return sp;
}

// One SNN step. grid = (NSLICES, NGROUPS), 256 threads (8 warps).
__global__ void k_step(const float* __restrict__ kh, int parity)
{
    extern __shared__ float2 sW[];   // [512][32] float2: (col lane, col lane+32)
    const unsigned* __restrict__ mr = parity ? g_maskB : g_maskA;
    unsigned*       __restrict__ mw = parity ? g_maskA : g_maskB;

    int slice = blockIdx.x;
    int group = blockIdx.y;
    int c0 = slice * SLICE_COLS;
    int t  = threadIdx.x;

    for (int idx = t; idx < NN * 32; idx += 256) {
        int j = idx >> 5, l = idx & 31;
        sW[idx] = make_float2(kh[j * NN + c0 + l], kh[j * NN + c0 + 32 + l]);
    }
    __syncthreads();

    int warp = t >> 5, lane = t & 31;

    for (int rr = warp; rr < GROUP_ROWS; rr += 8) {
        int b = group * GROUP_ROWS + rr;
        const uint4* mp = (const uint4*)(mr + b * 16);
        uint4 q0 = mp[0], q1 = mp[1], q2 = mp[2], q3 = mp[3];
        unsigned wds[16] = { q0.x, q0.y, q0.z, q0.w,
                             q1.x, q1.y, q1.z, q1.w,
                             q2.x, q2.y, q2.z, q2.w,
                             q3.x, q3.y, q3.z, q3.w };
        float acc0 = 0.0f, acc1 = 0.0f;
        #pragma unroll
        for (int w = 0; w < 16; w++) {
            unsigned m = wds[w];
            while (m) {                       // increasing-j order == sequential
                int j = __ffs((int)m) - 1;
                m &= m - 1;
                float2 wv = sW[((w << 5) + j) * 32 + lane];
                acc0 = __fadd_rn(acc0, wv.x);
                acc1 = __fadd_rn(acc1, wv.y);
            }
        }

        int cell0 = b * NN + c0 + lane;
        bool s0 = update_cell(cell0,      acc0);
        bool s1 = update_cell(cell0 + 32, acc1);

        unsigned bal0 = __ballot_sync(0xffffffffu, s0);
        unsigned bal1 = __ballot_sync(0xffffffffu, s1);
        if (lane == 0) {
            mw[b * 16 + slice * 2]     = bal0;
            mw[b * 16 + slice * 2 + 1] = bal1;
        }
    }
}

// ---------------------------------------------------------------------------
// out GEMM: out[b][o] = R_OUT * sum_n rate[b][n] * ko[n][o], sequential-k FMA
__global__ void k_out(const float* __restrict__ ko, float* __restrict__ outp)
{
    __shared__ float As[16][64];
    __shared__ float Bs[16][65];
    int bn0 = blockIdx.x * 64;
    int bm0 = blockIdx.y * 64;
    int t = threadIdx.x;
    int tx = t & 15, ty = t >> 4;
    float acc[4][4];
    #pragma unroll
    for (int i = 0; i < 4; i++)
        #pragma unroll
        for (int j = 0; j < 4; j++) acc[i][j] = 0.0f;

    for (int k0 = 0; k0 < NN; k0 += 16) {
        #pragma unroll
        for (int q = 0; q < 4; q++) {
            int li = t + q * 256;
            int i  = li >> 4;
            int kk = li & 15;
            As[kk][i] = g_rate[(bm0 + i) * NN + k0 + kk];
        }
        #pragma unroll
        for (int q = 0; q < 4; q++) {
            int li = t + q * 256;
            int kk = li >> 6;
            int n  = li & 63;
            Bs[kk][n] = ko[(k0 + kk) * OUT_DIMS + bn0 + n];
        }
        __syncthreads();
        #pragma unroll
        for (int kk = 0; kk < 16; kk++) {
            float a[4], bq[4];
            #pragma unroll
            for (int i = 0; i < 4; i++) a[i]  = As[kk][ty * 4 + i];
            #pragma unroll
            for (int j = 0; j < 4; j++) bq[j] = Bs[kk][tx * 4 + j];
            #pragma unroll
            for (int i = 0; i < 4; i++)
                #pragma unroll
                for (int j = 0; j < 4; j++)
                    acc[i][j] = fmaf(a[i], bq[j], acc[i][j]);
        }
        __syncthreads();
    }
    #pragma unroll
    for (int i = 0; i < 4; i++)
        #pragma unroll
        for (int j = 0; j < 4; j++)
            outp[(bm0 + ty * 4 + i) * OUT_DIMS + bn0 + tx * 4 + j] =
                __fmul_rn(R_OUT, acc[i][j]);
}

// ---------------------------------------------------------------------------
__global__ void k_copy(float* __restrict__ out)
{
    float* o_vm = out + BATCH * OUT_DIMS;
    float* o_is = o_vm + BATCH * NN;
    float* o_rt = o_is + BATCH * NN;
    float* o_sp = o_rt + BATCH * NN;
    int tid  = blockIdx.x * blockDim.x + threadIdx.x;
    int nthr = gridDim.x * blockDim.x;
    for (int i = tid; i < BATCH * NN; i += nthr) {
        o_vm[i] = g_vm[i];
        o_is[i] = g_isyn[i];
        o_rt[i] = g_rate[i];
        unsigned m = g_maskB[(i >> 9) * 16 + ((i & 511) >> 5)];
        o_sp[i] = ((m >> (i & 31)) & 1u) ? 1.0f : 0.0f;
    }
}

// ---------------------------------------------------------------------------
extern "C" void kernel_launch(void* const* d_in, const int* in_sizes, int n_in,
                              void* d_out, int out_size)
{
    const float* vm0 = (const float*)d_in[0];
    const float* is0 = (const float*)d_in[1];
    const float* rt0 = (const float*)d_in[2];
    const float* sp0 = (const float*)d_in[3];
    const float* x   = (const float*)d_in[4];
    const float* kin = (const float*)d_in[5];
    const float* kh  = (const float*)d_in[6];
    const float* ko  = (const float*)d_in[7];
    float* outp = (float*)d_out;

    const int smem = NN * 32 * (int)sizeof(float2);  // 128 KB
    cudaFuncSetAttribute(k_step, cudaFuncAttributeMaxDynamicSharedMemorySize, smem);

    k_init<<<256, 256>>>(vm0, is0, rt0, sp0);
    k_iin<<<dim3(NN / 64, BATCH / 64), 256>>>(x, kin);

    for (int s = 0; s < NSTEPS; s++)
        k_step<<<dim3(NSLICES, NGROUPS), 256, smem>>>(kh, s & 1);

    k_out<<<dim3(OUT_DIMS / 64, BATCH / 64), 256>>>(ko, outp);
    k_copy<<<512, 256>>>(outp);
}

// round 4
// speedup vs baseline: 2.9333x; 2.9333x over previous
#include <cuda_runtime.h>
#include <cstdint>

// ---------------------------------------------------------------------------
// SG_RSNN: 33-step recurrent spiking network. Bit-exact vs JAX/XLA:GPU ref:
//  * GEMMs: single sequential-k FMA chain per output element, post-mul R.
//  * spike @ kernel_h: sparse ascending-j plain adds (== dense chain, spike in {0,1}).
//  * LIF elementwise: fma shapes matching ptxas contraction of XLA mul/add.
// R4: k_step redesigned for latency hiding:
//  * 1024 threads (32 warps) per CTA, occ 12.5% -> 50%
//  * two-phase row processing: parallel mask decode -> smem index list,
//    then unrolled streaming accumulate (breaks the serial ffs chain).
// ---------------------------------------------------------------------------

#define BATCH    8192
#define IN_DIMS  256
#define NN       512
#define OUT_DIMS 128
#define NSTEPS   33

#define NSLICES  8
#define NGROUPS  16
#define GROUP_ROWS 512
#define SLICE_COLS 64
#define STEP_THREADS 1024
#define STEP_WARPS   32

#define ALPHA_SYN 0.90483741803595957f
#define ALPHA_VM  0.95122942450071401f
#define ALPHA_OUT 0.95122942450071401f
#define R_IN   0.08838834764831844f
#define R_H    0.125f
#define R_OUT  0.22097086912079611f
#define VTH    1.0f

__device__ float    g_iin [BATCH * NN];
__device__ float    g_vm  [BATCH * NN];
__device__ float    g_isyn[BATCH * NN];
__device__ float    g_rate[BATCH * NN];
__device__ unsigned g_maskA[BATCH * 16];
__device__ unsigned g_maskB[BATCH * 16];

// ---------------------------------------------------------------------------
__global__ void k_init(const float* __restrict__ vm0, const float* __restrict__ is0,
                       const float* __restrict__ rt0, const float* __restrict__ sp0)
{
    int tid  = blockIdx.x * blockDim.x + threadIdx.x;
    int nthr = gridDim.x * blockDim.x;
    for (int i = tid; i < BATCH * NN; i += nthr) {
        g_vm[i]   = vm0[i];
        g_isyn[i] = is0[i];
        g_rate[i] = rt0[i];
    }
    for (int w = tid; w < BATCH * 16; w += nthr) {
        int b = w >> 4, wi = w & 15;
        const float* sp = sp0 + b * NN + wi * 32;
        unsigned m = 0;
        #pragma unroll
        for (int j = 0; j < 32; j++)
            m |= (sp[j] != 0.0f ? 1u : 0u) << j;
        g_maskA[w] = m;
    }
}

// ---------------------------------------------------------------------------
// i_in GEMM: acc[b][n] = sum_{k=0..511} a_k * kin[k][n],  a = concat(x,-x)[b]
__global__ void k_iin(const float* __restrict__ x, const float* __restrict__ kin)
{
    __shared__ float As[16][64];
    __shared__ float Bs[16][65];
    int bn0 = blockIdx.x * 64;
    int bm0 = blockIdx.y * 64;
    int t = threadIdx.x;
    int tx = t & 15, ty = t >> 4;
    float acc[4][4];
    #pragma unroll
    for (int i = 0; i < 4; i++)
        #pragma unroll
        for (int j = 0; j < 4; j++) acc[i][j] = 0.0f;

    for (int k0 = 0; k0 < 2 * IN_DIMS; k0 += 16) {
        #pragma unroll
        for (int q = 0; q < 4; q++) {
            int li = t + q * 256;
            int i  = li >> 4;
            int kk = li & 15;
            int k  = k0 + kk;
            float xv = x[(bm0 + i) * IN_DIMS + (k & (IN_DIMS - 1))];
            As[kk][i] = (k < IN_DIMS) ? xv : -xv;
        }
        #pragma unroll
        for (int q = 0; q < 4; q++) {
            int li = t + q * 256;
            int kk = li >> 6;
            int n  = li & 63;
            Bs[kk][n] = kin[(k0 + kk) * NN + bn0 + n];
        }
        __syncthreads();
        #pragma unroll
        for (int kk = 0; kk < 16; kk++) {
            float a[4], bq[4];
            #pragma unroll
            for (int i = 0; i < 4; i++) a[i]  = As[kk][ty * 4 + i];
            #pragma unroll
            for (int j = 0; j < 4; j++) bq[j] = Bs[kk][tx * 4 + j];
            #pragma unroll
            for (int i = 0; i < 4; i++)
                #pragma unroll
                for (int j = 0; j < 4; j++)
                    acc[i][j] = fmaf(a[i], bq[j], acc[i][j]);
        }
        __syncthreads();
    }
    #pragma unroll
    for (int i = 0; i < 4; i++)
        #pragma unroll
        for (int j = 0; j < 4; j++)
            g_iin[(bm0 + ty * 4 + i) * NN + bn0 + tx * 4 + j] =
                __fmul_rn(R_IN, acc[i][j]);
}

// ---------------------------------------------------------------------------
__device__ __forceinline__ bool update_cell(int cell, float acc)
{
    float isyn = g_isyn[cell];
    float iin  = g_iin [cell];
    float v    = g_vm  [cell];
    float rate = g_rate[cell];

    float ispike = __fmul_rn(R_H, acc);
    isyn = fmaf(isyn, ALPHA_SYN, ispike);
    float s = __fadd_rn(isyn, iin);
    v = fmaf(ALPHA_VM, __fsub_rn(v, s), s);
    bool sp = v > VTH;
    v = sp ? 0.0f : v;
    float tgt = sp ? 2.0f : 0.0f;
    rate = fmaf(ALPHA_OUT, __fsub_rn(rate, tgt), tgt);

    g_isyn[cell] = isyn;
    g_vm  [cell] = v;
    g_rate[cell] = rate;
    return sp;
}

// One SNN step. grid=(NSLICES,NGROUPS), 1024 threads (32 warps).
// dyn smem: [ float2 sW[512*32] : 128KB ][ u16 sIdx[32][512] : 32KB ]
__global__ void __launch_bounds__(STEP_THREADS, 1)
k_step(const float* __restrict__ kh, int parity)
{
    extern __shared__ float2 sW[];
    unsigned short* sIdx = (unsigned short*)(sW + NN * 32);

    const unsigned* __restrict__ mr = parity ? g_maskB : g_maskA;
    unsigned*       __restrict__ mw = parity ? g_maskA : g_maskB;

    int slice = blockIdx.x;
    int group = blockIdx.y;
    int c0 = slice * SLICE_COLS;
    int t  = threadIdx.x;

    for (int idx = t; idx < NN * 32; idx += STEP_THREADS) {
        int j = idx >> 5, l = idx & 31;
        sW[idx] = make_float2(kh[j * NN + c0 + l], kh[j * NN + c0 + 32 + l]);
    }
    __syncthreads();

    int warp = t >> 5, lane = t & 31;
    unsigned short* myIdx = sIdx + warp * NN;
    const float2* sWl = sW + lane;    // lane-fixed base

    for (int rr = warp; rr < GROUP_ROWS; rr += STEP_WARPS) {
        int b = group * GROUP_ROWS + rr;

        // ---- phase 1: parallel decode of 16 mask words into ascending list
        unsigned m = (lane < 16) ? mr[b * 16 + lane] : 0u;
        int cnt = __popc(m);
        int off = cnt;
        #pragma unroll
        for (int d = 1; d < 32; d <<= 1) {
            int v = __shfl_up_sync(0xffffffffu, off, d);
            if (lane >= d) off += v;
        }
        int total = __shfl_sync(0xffffffffu, off, 31);
        off -= cnt;                    // exclusive prefix
        int jbase = lane << 5;
        while (m) {
            int j = __ffs((int)m) - 1;
            m &= m - 1;
            myIdx[off++] = (unsigned short)(jbase + j);
        }
        __syncwarp();

        // ---- phase 2: streaming accumulate in strict ascending order
        float acc0 = 0.0f, acc1 = 0.0f;
        int k = 0;
        for (; k + 4 <= total; k += 4) {
            int j0 = myIdx[k], j1 = myIdx[k+1], j2 = myIdx[k+2], j3 = myIdx[k+3];
            float2 w0 = sWl[j0 << 5];
            float2 w1 = sWl[j1 << 5];
            float2 w2 = sWl[j2 << 5];
            float2 w3 = sWl[j3 << 5];
            acc0 = __fadd_rn(acc0, w0.x); acc1 = __fadd_rn(acc1, w0.y);
            acc0 = __fadd_rn(acc0, w1.x); acc1 = __fadd_rn(acc1, w1.y);
            acc0 = __fadd_rn(acc0, w2.x); acc1 = __fadd_rn(acc1, w2.y);
            acc0 = __fadd_rn(acc0, w3.x); acc1 = __fadd_rn(acc1, w3.y);
        }
        for (; k < total; k++) {
            float2 wv = sWl[((int)myIdx[k]) << 5];
            acc0 = __fadd_rn(acc0, wv.x);
            acc1 = __fadd_rn(acc1, wv.y);
        }

        int cell0 = b * NN + c0 + lane;
        bool s0 = update_cell(cell0,      acc0);
        bool s1 = update_cell(cell0 + 32, acc1);

        unsigned bal0 = __ballot_sync(0xffffffffu, s0);
        unsigned bal1 = __ballot_sync(0xffffffffu, s1);
        if (lane == 0) {
            mw[b * 16 + slice * 2]     = bal0;
            mw[b * 16 + slice * 2 + 1] = bal1;
        }
    }
}

// ---------------------------------------------------------------------------
__global__ void k_out(const float* __restrict__ ko, float* __restrict__ outp)
{
    __shared__ float As[16][64];
    __shared__ float Bs[16][65];
    int bn0 = blockIdx.x * 64;
    int bm0 = blockIdx.y * 64;
    int t = threadIdx.x;
    int tx = t & 15, ty = t >> 4;
    float acc[4][4];
    #pragma unroll
    for (int i = 0; i < 4; i++)
        #pragma unroll
        for (int j = 0; j < 4; j++) acc[i][j] = 0.0f;

    for (int k0 = 0; k0 < NN; k0 += 16) {
        #pragma unroll
        for (int q = 0; q < 4; q++) {
            int li = t + q * 256;
            int i  = li >> 4;
            int kk = li & 15;
            As[kk][i] = g_rate[(bm0 + i) * NN + k0 + kk];
        }
        #pragma unroll
        for (int q = 0; q < 4; q++) {
            int li = t + q * 256;
            int kk = li >> 6;
            int n  = li & 63;
            Bs[kk][n] = ko[(k0 + kk) * OUT_DIMS + bn0 + n];
        }
        __syncthreads();
        #pragma unroll
        for (int kk = 0; kk < 16; kk++) {
            float a[4], bq[4];
            #pragma unroll
            for (int i = 0; i < 4; i++) a[i]  = As[kk][ty * 4 + i];
            #pragma unroll
            for (int j = 0; j < 4; j++) bq[j] = Bs[kk][tx * 4 + j];
            #pragma unroll
            for (int i = 0; i < 4; i++)
                #pragma unroll
                for (int j = 0; j < 4; j++)
                    acc[i][j] = fmaf(a[i], bq[j], acc[i][j]);
        }
        __syncthreads();
    }
    #pragma unroll
    for (int i = 0; i < 4; i++)
        #pragma unroll
        for (int j = 0; j < 4; j++)
            outp[(bm0 + ty * 4 + i) * OUT_DIMS + bn0 + tx * 4 + j] =
                __fmul_rn(R_OUT, acc[i][j]);
}

// ---------------------------------------------------------------------------
__global__ void k_copy(float* __restrict__ out)
{
    float* o_vm = out + BATCH * OUT_DIMS;
    float* o_is = o_vm + BATCH * NN;
    float* o_rt = o_is + BATCH * NN;
    float* o_sp = o_rt + BATCH * NN;
    int tid  = blockIdx.x * blockDim.x + threadIdx.x;
    int nthr = gridDim.x * blockDim.x;
    for (int i = tid; i < BATCH * NN; i += nthr) {
        o_vm[i] = g_vm[i];
        o_is[i] = g_isyn[i];
        o_rt[i] = g_rate[i];
        unsigned m = g_maskB[(i >> 9) * 16 + ((i & 511) >> 5)];
        o_sp[i] = ((m >> (i & 31)) & 1u) ? 1.0f : 0.0f;
    }
}

// ---------------------------------------------------------------------------
extern "C" void kernel_launch(void* const* d_in, const int* in_sizes, int n_in,
                              void* d_out, int out_size)
{
    const float* vm0 = (const float*)d_in[0];
    const float* is0 = (const float*)d_in[1];
    const float* rt0 = (const float*)d_in[2];
    const float* sp0 = (const float*)d_in[3];
    const float* x   = (const float*)d_in[4];
    const float* kin = (const float*)d_in[5];
    const float* kh  = (const float*)d_in[6];
    const float* ko  = (const float*)d_in[7];
    float* outp = (float*)d_out;

    const int smem = NN * 32 * (int)sizeof(float2)          // weights 128KB
                   + STEP_WARPS * NN * (int)sizeof(short);  // idx lists 32KB
    cudaFuncSetAttribute(k_step, cudaFuncAttributeMaxDynamicSharedMemorySize, smem);

    k_init<<<256, 256>>>(vm0, is0, rt0, sp0);
    k_iin<<<dim3(NN / 64, BATCH / 64), 256>>>(x, kin);

    for (int s = 0; s < NSTEPS; s++)
        k_step<<<dim3(NSLICES, NGROUPS), STEP_THREADS, smem>>>(kh, s & 1);

    k_out<<<dim3(OUT_DIMS / 64, BATCH / 64), 256>>>(ko, outp);
    k_copy<<<512, 256>>>(outp);
}